// round 7
// baseline (speedup 1.0000x reference)
#include <cuda_runtime.h>
#include <cstdint>

namespace {

constexpr int NB = 4, DIN = 4000, DE = 128, DB = 8;
constexpr int KD = DIN + DE + DB;   // 4136
constexpr int MD = 512;
constexpr float ALPHA = 0.3f;
constexpr int NSLAB = 130;          // 129 x 32K + 1 x 8K(zero-padded to 32)
constexpr int SLAB_BYTES = 16384;   // one fragment image (A or B) per slab per tile
constexpr int NBUF = 4;             // B-only smem ring
constexpr int SMEM_MAIN = NBUF * SLAB_BYTES;   // 64KB

// fragment-image scratch (+2 pad slabs for A register-prefetch overrun)
__device__ __align__(16) uint8_t g_Afrag[(size_t)NB * 32 * NSLAB * SLAB_BYTES
                                         + 2 * SLAB_BYTES];                     // ~272.6MB
__device__ __align__(16) uint8_t g_Wfrag[(size_t)NB * 4  * NSLAB * SLAB_BYTES]; // 34MB

__device__ __forceinline__ uint32_t tf32r(float f) {
    uint32_t u;
    asm("cvt.rna.tf32.f32 %0, %1;" : "=r"(u) : "f"(f));
    return u;
}
__device__ __forceinline__ uint32_t smem_u32(const void* p) {
    uint32_t a;
    asm("{ .reg .u64 t; cvta.to.shared.u64 t, %1; cvt.u32.u64 %0, t; }" : "=r"(a) : "l"(p));
    return a;
}
__device__ __forceinline__ void sts32(uint32_t a, uint32_t v) {
    asm volatile("st.shared.b32 [%0], %1;" :: "r"(a), "r"(v) : "memory");
}
__device__ __forceinline__ void lds128(uint32_t a, uint32_t* r) {
    asm volatile("ld.shared.v4.b32 {%0,%1,%2,%3}, [%4];"
                 : "=r"(r[0]), "=r"(r[1]), "=r"(r[2]), "=r"(r[3]) : "r"(a));
}
__device__ __forceinline__ void ldg128(const void* g, uint32_t* r) {
    asm volatile("ld.global.nc.v4.b32 {%0,%1,%2,%3}, [%4];"
                 : "=r"(r[0]), "=r"(r[1]), "=r"(r[2]), "=r"(r[3]) : "l"(g));
}
__device__ __forceinline__ void mma8(float* d, const uint32_t* a, uint32_t b0, uint32_t b1) {
    asm volatile(
        "mma.sync.aligned.m16n8k8.row.col.f32.tf32.tf32.f32 "
        "{%0,%1,%2,%3}, {%4,%5,%6,%7}, {%8,%9}, {%0,%1,%2,%3};"
        : "+f"(d[0]), "+f"(d[1]), "+f"(d[2]), "+f"(d[3])
        : "r"(a[0]), "r"(a[1]), "r"(a[2]), "r"(a[3]), "r"(b0), "r"(b1));
}
__device__ __forceinline__ void cp16(uint32_t saddr, const void* gaddr) {
    asm volatile("cp.async.cg.shared.global [%0], [%1], 16;"
                 :: "r"(saddr), "l"(gaddr) : "memory");
}
#define CP_COMMIT() asm volatile("cp.async.commit_group;" ::: "memory")
#define CP_WAIT2()  asm volatile("cp.async.wait_group 2;" ::: "memory")

// fragment offsets within one 16KB slab image
__device__ __forceinline__ uint32_t fr_off(int ks, int f, int slot) {
    return (uint32_t)(((ks * 8 + f) * 32 + slot) << 4);
}

// ======================= prep A: x|embed|batches -> tf32 fragment image =======================
__global__ void __launch_bounds__(256)
prep_a(const float* __restrict__ x, const uint32_t* __restrict__ mask,
       const float* __restrict__ embed, const float* __restrict__ batches,
       const float* __restrict__ mean)
{
    __shared__ uint32_t sf[4096];
    const int s  = blockIdx.x;
    const int rt = blockIdx.y;
    const int b  = blockIdx.z;
    const int rB = rt * 128;
    const int t  = threadIdx.x;
    const uint32_t base = smem_u32(sf);
    const int k0 = s * 32;

    if (s < 125) {                       // x region: batch all 12 LDG128 first
        float4 xv[4]; uint4 mv[4]; float4 mu[4];
#pragma unroll
        for (int p = 0; p < 4; p++) {
            const int idx = p * 256 + t;
            const int row = idx >> 3, q = idx & 7;
            const size_t gx = (size_t)(rB + row) * (NB * DIN) + (size_t)b * DIN + k0 + q * 4;
            xv[p] = *reinterpret_cast<const float4*>(x + gx);
            mv[p] = *reinterpret_cast<const uint4*>(mask + gx);
            mu[p] = *reinterpret_cast<const float4*>(mean + b * DIN + k0 + q * 4);
        }
#pragma unroll
        for (int p = 0; p < 4; p++) {
            const int idx = p * 256 + t;
            const int row = idx >> 3, q = idx & 7;
            uint32_t v[4];
            v[0] = mv[p].x ? tf32r(xv[p].x - mu[p].x) : 0u;
            v[1] = mv[p].y ? tf32r(xv[p].y - mu[p].y) : 0u;
            v[2] = mv[p].z ? tf32r(xv[p].z - mu[p].z) : 0u;
            v[3] = mv[p].w ? tf32r(xv[p].w - mu[p].w) : 0u;
            const int ks = q >> 1, mf = row >> 4, rin = row & 15;
            const int g = rin & 7, reg = (rin >> 3) + 2 * (q & 1);
#pragma unroll
            for (int i = 0; i < 4; i++)
                sts32(base + fr_off(ks, mf, (g * 4 + i) ^ ks) + reg * 4, v[i]);
        }
    } else if (s < 129) {                // embed region
        float4 ev[4];
#pragma unroll
        for (int p = 0; p < 4; p++) {
            const int idx = p * 256 + t;
            const int row = idx >> 3, q = idx & 7;
            ev[p] = *reinterpret_cast<const float4*>(
                embed + (size_t)(rB + row) * (NB * DE) + b * DE + (k0 - DIN) + q * 4);
        }
#pragma unroll
        for (int p = 0; p < 4; p++) {
            const int idx = p * 256 + t;
            const int row = idx >> 3, q = idx & 7;
            const uint32_t v[4] = {tf32r(ev[p].x), tf32r(ev[p].y),
                                   tf32r(ev[p].z), tf32r(ev[p].w)};
            const int ks = q >> 1, mf = row >> 4, rin = row & 15;
            const int g = rin & 7, reg = (rin >> 3) + 2 * (q & 1);
#pragma unroll
            for (int i = 0; i < 4; i++)
                sts32(base + fr_off(ks, mf, (g * 4 + i) ^ ks) + reg * 4, v[i]);
        }
    } else {                             // batches tail: zero-pad, then ks=0 frags
        const float4 bv = *reinterpret_cast<const float4*>(
            batches + (size_t)(rB + (t >> 1)) * DB + (t & 1) * 4);
        for (int i = t; i < 4096; i += 256) sf[i] = 0;
        __syncthreads();
        const int row = t >> 1, q = t & 1;
        const uint32_t v[4] = {tf32r(bv.x), tf32r(bv.y), tf32r(bv.z), tf32r(bv.w)};
        const int mf = row >> 4, rin = row & 15;
        const int g = rin & 7, reg = (rin >> 3) + 2 * q;
#pragma unroll
        for (int i = 0; i < 4; i++)
            sts32(base + fr_off(0, mf, g * 4 + i) + reg * 4, v[i]);
    }
    __syncthreads();

    uint4* dst = reinterpret_cast<uint4*>(
        g_Afrag + ((size_t)(b * 32 + rt) * NSLAB + s) * SLAB_BYTES);
    const uint4* src = reinterpret_cast<const uint4*>(sf);
#pragma unroll
    for (int i = 0; i < 4; i++) dst[i * 256 + t] = src[i * 256 + t];
}

// ======================= prep W: W -> tf32 fragment image =======================
__global__ void __launch_bounds__(256)
prep_w(const float* __restrict__ W)
{
    __shared__ uint32_t sf[4096];
    const int s   = blockIdx.x;
    const int cbi = blockIdx.y;
    const int b   = blockIdx.z;
    const int t   = threadIdx.x;
    const uint32_t base = smem_u32(sf);
    const int k0 = s * 32;
    const float* Wb = W + (size_t)b * KD * MD + cbi * 128;

    if (s < 129) {
        float4 wv[4];
#pragma unroll
        for (int p = 0; p < 4; p++) {
            const int idx = p * 256 + t;
            const int krow = idx >> 5, n0 = (idx & 31) * 4;
            wv[p] = *reinterpret_cast<const float4*>(Wb + (size_t)(k0 + krow) * MD + n0);
        }
#pragma unroll
        for (int p = 0; p < 4; p++) {
            const int idx = p * 256 + t;
            const int krow = idx >> 5, n0 = (idx & 31) * 4;
            const uint32_t v[4] = {tf32r(wv[p].x), tf32r(wv[p].y),
                                   tf32r(wv[p].z), tf32r(wv[p].w)};
            const int ks = krow >> 3, tk = krow & 3, kh = (krow >> 2) & 1;
#pragma unroll
            for (int i = 0; i < 4; i++) {
                const int n = n0 + i, g = n & 7, nf = n >> 3, np = nf >> 1;
                const int reg = (nf & 1) * 2 + kh;
                sts32(base + fr_off(ks, np, (g * 4 + tk) ^ np) + reg * 4, v[i]);
            }
        }
    } else {
        const int krow = t >> 5, n0 = (t & 31) * 4;
        const float4 wv4 = *reinterpret_cast<const float4*>(
            Wb + (size_t)(k0 + krow) * MD + n0);
        for (int i = t; i < 4096; i += 256) sf[i] = 0;
        __syncthreads();
        const uint32_t v[4] = {tf32r(wv4.x), tf32r(wv4.y), tf32r(wv4.z), tf32r(wv4.w)};
        const int tk = krow & 3, kh = (krow >> 2) & 1;
#pragma unroll
        for (int i = 0; i < 4; i++) {
            const int n = n0 + i, g = n & 7, nf = n >> 3, np = nf >> 1;
            const int reg = (nf & 1) * 2 + kh;
            sts32(base + fr_off(0, np, (g * 4 + tk) ^ np) + reg * 4, v[i]);
        }
    }
    __syncthreads();

    uint4* dst = reinterpret_cast<uint4*>(
        g_Wfrag + ((size_t)(b * 4 + cbi) * NSLAB + s) * SLAB_BYTES);
    const uint4* src = reinterpret_cast<const uint4*>(sf);
#pragma unroll
    for (int i = 0; i < 4; i++) dst[i * 256 + t] = src[i * 256 + t];
}

// ======================= main: A via direct LDG prefetch, B via cp.async ring =======================
__global__ void __launch_bounds__(256, 2)
ib_main(const float* __restrict__ bias, float* __restrict__ out)
{
    extern __shared__ char smem[];
    const uint32_t sb = smem_u32(smem);
    const int t    = threadIdx.x;
    const int lane = t & 31;
    const int wid  = t >> 5;
    const int wm   = wid & 3;
    const int wn   = wid >> 2;
    const int cbi  = blockIdx.x;
    const int rt   = blockIdx.y;
    const int b    = blockIdx.z;
    const int rB   = rt * 128;
    const int cB   = cbi * 128;

    const uint8_t* gA = g_Afrag + (size_t)(b * 32 + rt) * NSLAB * SLAB_BYTES;
    const uint8_t* gW = g_Wfrag + (size_t)(b * 4 + cbi) * NSLAB * SLAB_BYTES;

    float acc[2][8][4];
#pragma unroll
    for (int m = 0; m < 2; m++)
#pragma unroll
        for (int n = 0; n < 8; n++)
#pragma unroll
            for (int q = 0; q < 4; q++) acc[m][n][q] = 0.f;

    // B-only smem ring
    auto cp_slab = [&](int s) {
        const uint32_t buf = sb + (uint32_t)((s % NBUF) * SLAB_BYTES);
        const uint8_t* ws = gW + (size_t)s * SLAB_BYTES;
#pragma unroll
        for (int i = 0; i < 4; i++) {
            const uint32_t off = (uint32_t)(i * 256 + t) * 16;
            cp16(buf + off, ws + off);
        }
    };

    // A fragment prefetch: global index k in [0, 520), 2-deep register ring
    uint32_t apre[2][2][4];
    auto ld_a = [&](int k, uint32_t dst[2][4]) {
        const int ks = k & 3;
        const uint8_t* p = gA + (size_t)(k >> 2) * SLAB_BYTES;
#pragma unroll
        for (int m = 0; m < 2; m++)
            ldg128(p + fr_off(ks, wm * 2 + m, lane ^ ks), dst[m]);
    };

    auto consume = [&](uint32_t buf, int ks, uint32_t afr[2][4]) {
        uint32_t bfr[4][4];
#pragma unroll
        for (int pp = 0; pp < 4; pp++) {
            const int np = wn * 4 + pp;
            lds128(buf + fr_off(ks, np, lane ^ np), bfr[pp]);
        }
#pragma unroll
        for (int m = 0; m < 2; m++)
#pragma unroll
            for (int pp = 0; pp < 4; pp++) {
                mma8(acc[m][2 * pp],     afr[m], bfr[pp][0], bfr[pp][1]);
                mma8(acc[m][2 * pp + 1], afr[m], bfr[pp][2], bfr[pp][3]);
            }
    };

    // prologue: 3 B slabs in flight, 2 A k-steps prefetched
    cp_slab(0); CP_COMMIT();
    cp_slab(1); CP_COMMIT();
    cp_slab(2); CP_COMMIT();
    ld_a(0, apre[0]);
    ld_a(1, apre[1]);

    for (int s = 0; s < NSLAB; s++) {
        CP_WAIT2();               // B slab s resident (2 newer groups pending)
        __syncthreads();          // all warps done with slab s-1's buffer
        if (s + 3 < NSLAB) cp_slab(s + 3);
        CP_COMMIT();              // one group per iteration
        const uint32_t buf = sb + (uint32_t)((s % NBUF) * SLAB_BYTES);
#pragma unroll
        for (int ks = 0; ks < 4; ks++) {
            const int k = s * 4 + ks;
            consume(buf, ks, apre[k & 1]);
            ld_a(k + 2, apre[k & 1]);   // prefetch (pad slabs absorb overrun)
        }
    }

    // -------- epilogue: bias + LeakyReLU --------
    const int g  = lane >> 2;
    const int tq = lane & 3;
#pragma unroll
    for (int m = 0; m < 2; m++) {
        const int r0 = rB + wm * 32 + m * 16 + g;
#pragma unroll
        for (int nf = 0; nf < 8; nf++) {
            const int col = cB + wn * 64 + nf * 8 + tq * 2;
            const float2 bv = *reinterpret_cast<const float2*>(bias + b * MD + col);
            float v0 = acc[m][nf][0] + bv.x;
            float v1 = acc[m][nf][1] + bv.y;
            float v2 = acc[m][nf][2] + bv.x;
            float v3 = acc[m][nf][3] + bv.y;
            v0 = (v0 >= 0.f) ? v0 : ALPHA * v0;
            v1 = (v1 >= 0.f) ? v1 : ALPHA * v1;
            v2 = (v2 >= 0.f) ? v2 : ALPHA * v2;
            v3 = (v3 >= 0.f) ? v3 : ALPHA * v3;
            *reinterpret_cast<float2*>(out + (size_t)r0 * (NB * MD) + b * MD + col)
                = make_float2(v0, v1);
            *reinterpret_cast<float2*>(out + (size_t)(r0 + 8) * (NB * MD) + b * MD + col)
                = make_float2(v2, v3);
        }
    }
}

} // namespace

extern "C" void kernel_launch(void* const* d_in, const int* in_sizes, int n_in,
                              void* d_out, int out_size)
{
    const float*    x       = (const float*)d_in[0];
    const uint32_t* mask    = (const uint32_t*)d_in[1];
    const float*    embed   = (const float*)d_in[2];
    const float*    batches = (const float*)d_in[3];
    const float*    mean    = (const float*)d_in[4];
    const float*    W       = (const float*)d_in[5];
    const float*    bias    = (const float*)d_in[6];
    float*          out     = (float*)d_out;

    prep_w<<<dim3(NSLAB, 4, NB), 256>>>(W);
    prep_a<<<dim3(NSLAB, 32, NB), 256>>>(x, mask, embed, batches, mean);

    cudaFuncSetAttribute(ib_main, cudaFuncAttributeMaxDynamicSharedMemorySize, SMEM_MAIN);
    ib_main<<<dim3(4, 32, NB), 256, SMEM_MAIN>>>(bias, out);
}

// round 8
// speedup vs baseline: 1.6803x; 1.6803x over previous
#include <cuda_runtime.h>
#include <cstdint>

namespace {

constexpr int NB = 4, DIN = 4000, DE = 128, DB = 8;
constexpr int KD = DIN + DE + DB;   // 4136
constexpr int MD = 512;
constexpr float ALPHA = 0.3f;
constexpr int NSLAB = 130;          // 129 x 32K + 1 x 8K (zero-padded to 32)
constexpr int IMG_BYTES  = 8192;    // one fp16 fragment image (A or B) per slab per tile
constexpr int SLAB_BYTES = 2 * IMG_BYTES;      // A + B = 16KB
constexpr int NBUF = 6;
constexpr int SMEM_MAIN = NBUF * SLAB_BYTES;   // 96KB

__device__ __align__(16) uint8_t g_Afrag[(size_t)NB * 32 * NSLAB * IMG_BYTES]; // 136MB
__device__ __align__(16) uint8_t g_Wfrag[(size_t)NB * 4  * NSLAB * IMG_BYTES]; // 17MB

__device__ __forceinline__ uint32_t h2pack(float lo, float hi) {  // lo -> low 16 bits
    uint32_t u;
    asm("cvt.rn.f16x2.f32 %0, %1, %2;" : "=r"(u) : "f"(hi), "f"(lo));
    return u;
}
__device__ __forceinline__ uint32_t smem_u32(const void* p) {
    uint32_t a;
    asm("{ .reg .u64 t; cvta.to.shared.u64 t, %1; cvt.u32.u64 %0, t; }" : "=r"(a) : "l"(p));
    return a;
}
__device__ __forceinline__ void sts32(uint32_t a, uint32_t v) {
    asm volatile("st.shared.b32 [%0], %1;" :: "r"(a), "r"(v) : "memory");
}
__device__ __forceinline__ void sts64(uint32_t a, uint32_t v0, uint32_t v1) {
    asm volatile("st.shared.v2.b32 [%0], {%1,%2};" :: "r"(a), "r"(v0), "r"(v1) : "memory");
}
__device__ __forceinline__ void lds128(uint32_t a, uint32_t* r) {
    asm volatile("ld.shared.v4.b32 {%0,%1,%2,%3}, [%4];"
                 : "=r"(r[0]), "=r"(r[1]), "=r"(r[2]), "=r"(r[3]) : "r"(a));
}
__device__ __forceinline__ void mma16(float* d, const uint32_t* a, uint32_t b0, uint32_t b1) {
    asm volatile(
        "mma.sync.aligned.m16n8k16.row.col.f32.f16.f16.f32 "
        "{%0,%1,%2,%3}, {%4,%5,%6,%7}, {%8,%9}, {%0,%1,%2,%3};"
        : "+f"(d[0]), "+f"(d[1]), "+f"(d[2]), "+f"(d[3])
        : "r"(a[0]), "r"(a[1]), "r"(a[2]), "r"(a[3]), "r"(b0), "r"(b1));
}
__device__ __forceinline__ void cp16(uint32_t saddr, const void* gaddr) {
    asm volatile("cp.async.cg.shared.global [%0], [%1], 16;"
                 :: "r"(saddr), "l"(gaddr) : "memory");
}
#define CP_COMMIT() asm volatile("cp.async.commit_group;" ::: "memory")
#define CP_WAIT4()  asm volatile("cp.async.wait_group 4;" ::: "memory")

// ======================= merged prep: A tiles (y<32) + W tiles (y>=32) =======================
// A image layout: [ks(2)][mf(8)][slot(32)] x 16B, slot = rawlane ^ ks
//   rawlane l: a0=A[mf*16 + (l>>2)][2(l&3), +1] lo bytes, a1=row+8 lo, a2/a3 = k+8 (hi 8 bytes)
// B image layout: [ks(2)][np(8)][slot(32)] x 16B, slot = rawlane ^ np
//   16B = {b0(nf=2np), b1(nf=2np), b0(nf=2np+1), b1(nf=2np+1)}
__global__ void __launch_bounds__(256)
prep_all(const float* __restrict__ x, const uint32_t* __restrict__ mask,
         const float* __restrict__ embed, const float* __restrict__ batches,
         const float* __restrict__ mean, const float* __restrict__ W)
{
    __shared__ uint32_t sf[2048];    // 8KB image
    const int s  = blockIdx.x;
    const int y  = blockIdx.y;
    const int b  = blockIdx.z;
    const int t  = threadIdx.x;
    const uint32_t base = smem_u32(sf);
    const int k0 = s * 32;

    if (y < 32) {
        // ---------------- A tile ----------------
        const int rB = y * 128;
        if (s < 129) {
            float4 xlo[2], xhi[2], mu[2];
            uint4  mlo[2], mhi[2];
            const bool xreg = (s < 125);
#pragma unroll
            for (int p = 0; p < 2; p++) {
                const int unit = p * 256 + t;
                const int q = unit & 7, pr = unit >> 3;
                const int mf = pr >> 3, rr = pr & 7;
                const int rlo = rB + mf * 16 + rr, rhi = rlo + 8;
                if (xreg) {
                    const int gk = k0 + q * 4;
                    const size_t glo = (size_t)rlo * (NB * DIN) + (size_t)b * DIN + gk;
                    const size_t ghi = (size_t)rhi * (NB * DIN) + (size_t)b * DIN + gk;
                    xlo[p] = *reinterpret_cast<const float4*>(x + glo);
                    xhi[p] = *reinterpret_cast<const float4*>(x + ghi);
                    mlo[p] = *reinterpret_cast<const uint4*>(mask + glo);
                    mhi[p] = *reinterpret_cast<const uint4*>(mask + ghi);
                    mu[p]  = *reinterpret_cast<const float4*>(mean + b * DIN + gk);
                } else {
                    const int e = k0 - DIN + q * 4;
                    xlo[p] = *reinterpret_cast<const float4*>(
                        embed + (size_t)rlo * (NB * DE) + b * DE + e);
                    xhi[p] = *reinterpret_cast<const float4*>(
                        embed + (size_t)rhi * (NB * DE) + b * DE + e);
                }
            }
#pragma unroll
            for (int p = 0; p < 2; p++) {
                const int unit = p * 256 + t;
                const int q = unit & 7, pr = unit >> 3;
                const int mf = pr >> 3, rr = pr & 7;
                float vl[4], vh[4];
                if (xreg) {
                    vl[0] = mlo[p].x ? xlo[p].x - mu[p].x : 0.f;
                    vl[1] = mlo[p].y ? xlo[p].y - mu[p].y : 0.f;
                    vl[2] = mlo[p].z ? xlo[p].z - mu[p].z : 0.f;
                    vl[3] = mlo[p].w ? xlo[p].w - mu[p].w : 0.f;
                    vh[0] = mhi[p].x ? xhi[p].x - mu[p].x : 0.f;
                    vh[1] = mhi[p].y ? xhi[p].y - mu[p].y : 0.f;
                    vh[2] = mhi[p].z ? xhi[p].z - mu[p].z : 0.f;
                    vh[3] = mhi[p].w ? xhi[p].w - mu[p].w : 0.f;
                } else {
                    vl[0] = xlo[p].x; vl[1] = xlo[p].y; vl[2] = xlo[p].z; vl[3] = xlo[p].w;
                    vh[0] = xhi[p].x; vh[1] = xhi[p].y; vh[2] = xhi[p].z; vh[3] = xhi[p].w;
                }
                const uint32_t h0 = h2pack(vl[0], vl[1]);   // a-lo for pair lane pl
                const uint32_t h1 = h2pack(vh[0], vh[1]);
                const uint32_t h2 = h2pack(vl[2], vl[3]);   // pair lane pl+1
                const uint32_t h3 = h2pack(vh[2], vh[3]);
                const int ks = q >> 2, hi = (q >> 1) & 1, pl = 2 * (q & 1);
                const uint32_t s0 = (uint32_t)((rr * 4 + pl) ^ ks);
                const uint32_t s1 = (uint32_t)((rr * 4 + pl + 1) ^ ks);
                const uint32_t fb = base + (uint32_t)((ks * 8 + mf) * 32) * 16 + hi * 8;
                sts64(fb + s0 * 16, h0, h1);
                sts64(fb + s1 * 16, h2, h3);
            }
        } else {
            // batches tail: zero image, fill lo half of ks=0
            float4 blo, bhi;
            int mf = 0, rr = 0, q = 0;
            if (t < 128) {
                const int pr = t >> 1;
                q = t & 1; mf = pr >> 3; rr = pr & 7;
                const int rlo = rB + mf * 16 + rr;
                blo = *reinterpret_cast<const float4*>(batches + (size_t)rlo * DB + q * 4);
                bhi = *reinterpret_cast<const float4*>(batches + (size_t)(rlo + 8) * DB + q * 4);
            }
            for (int i = t; i < 2048; i += 256) sf[i] = 0;
            __syncthreads();
            if (t < 128) {
                const uint32_t h0 = h2pack(blo.x, blo.y);
                const uint32_t h1 = h2pack(bhi.x, bhi.y);
                const uint32_t h2 = h2pack(blo.z, blo.w);
                const uint32_t h3 = h2pack(bhi.z, bhi.w);
                const int pl = 2 * q;          // kpair 0,1 (q=0) / 2,3 (q=1), hi=0, ks=0
                const uint32_t fb = base + (uint32_t)(mf * 32) * 16;
                sts64(fb + (uint32_t)(rr * 4 + pl) * 16, h0, h1);
                sts64(fb + (uint32_t)(rr * 4 + pl + 1) * 16, h2, h3);
            }
        }
        __syncthreads();
        uint4* dst = reinterpret_cast<uint4*>(
            g_Afrag + ((size_t)(b * 32 + y) * NSLAB + s) * IMG_BYTES);
        const uint4* src = reinterpret_cast<const uint4*>(sf);
        dst[t] = src[t];
        dst[256 + t] = src[256 + t];
    } else {
        // ---------------- W tile ----------------
        const int cbi = y - 32;
        const float* Wb = W + (size_t)b * KD * MD + cbi * 128;
        if (s < 129) {
            float4 w0[2], w1[2];
#pragma unroll
            for (int p = 0; p < 2; p++) {
                const int unit = p * 256 + t;
                const int kp = unit >> 5, n0 = (unit & 31) * 4;
                const int k = k0 + kp * 2;
                w0[p] = *reinterpret_cast<const float4*>(Wb + (size_t)k * MD + n0);
                w1[p] = *reinterpret_cast<const float4*>(Wb + (size_t)(k + 1) * MD + n0);
            }
#pragma unroll
            for (int p = 0; p < 2; p++) {
                const int unit = p * 256 + t;
                const int kp = unit >> 5, n0 = (unit & 31) * 4;
                const int ks = kp >> 3, kpi = kp & 7;
                const int tk = kpi & 3, hi = kpi >> 2;
                const uint32_t h[4] = {h2pack(w0[p].x, w1[p].x), h2pack(w0[p].y, w1[p].y),
                                       h2pack(w0[p].z, w1[p].z), h2pack(w0[p].w, w1[p].w)};
#pragma unroll
                for (int i = 0; i < 4; i++) {
                    const int n = n0 + i, col = n & 7, nf = n >> 3, np = nf >> 1;
                    const int reg = (nf & 1) * 2 + hi;
                    const int slot = (col * 4 + tk) ^ np;
                    sts32(base + (uint32_t)(((ks * 8 + np) * 32 + slot) * 16 + reg * 4),
                          h[i]);
                }
            }
        } else {
            float4 w0, w1;
            int kp = 0, n0 = 0;
            if (t < 128) {
                kp = t >> 5; n0 = (t & 31) * 4;
                const int k = k0 + kp * 2;
                w0 = *reinterpret_cast<const float4*>(Wb + (size_t)k * MD + n0);
                w1 = *reinterpret_cast<const float4*>(Wb + (size_t)(k + 1) * MD + n0);
            }
            for (int i = t; i < 2048; i += 256) sf[i] = 0;
            __syncthreads();
            if (t < 128) {
                const int tk = kp & 3;        // kp 0..3 -> ks=0, hi=0
                const uint32_t h[4] = {h2pack(w0.x, w1.x), h2pack(w0.y, w1.y),
                                       h2pack(w0.z, w1.z), h2pack(w0.w, w1.w)};
#pragma unroll
                for (int i = 0; i < 4; i++) {
                    const int n = n0 + i, col = n & 7, nf = n >> 3, np = nf >> 1;
                    const int reg = (nf & 1) * 2;
                    const int slot = (col * 4 + tk) ^ np;
                    sts32(base + (uint32_t)((np * 32 + slot) * 16 + reg * 4), h[i]);
                }
            }
        }
        __syncthreads();
        uint4* dst = reinterpret_cast<uint4*>(
            g_Wfrag + ((size_t)(b * 4 + cbi) * NSLAB + s) * IMG_BYTES);
        const uint4* src = reinterpret_cast<const uint4*>(sf);
        dst[t] = src[t];
        dst[256 + t] = src[256 + t];
    }
}

// ======================= main: cp.async 5-deep pipeline + fp16 HMMA =======================
__global__ void __launch_bounds__(256, 2)
ib_main(const float* __restrict__ bias, float* __restrict__ out)
{
    extern __shared__ char smem[];
    const uint32_t sb = smem_u32(smem);
    const int t    = threadIdx.x;
    const int lane = t & 31;
    const int wid  = t >> 5;
    const int wm   = wid & 3;        // 32 rows each
    const int wn   = wid >> 2;       // 64 cols each
    const int cbi  = blockIdx.x;
    const int rt   = blockIdx.y;
    const int b    = blockIdx.z;
    const int rB   = rt * 128;
    const int cB   = cbi * 128;

    const uint8_t* gA = g_Afrag + (size_t)(b * 32 + rt) * NSLAB * IMG_BYTES;
    const uint8_t* gW = g_Wfrag + (size_t)(b * 4 + cbi) * NSLAB * IMG_BYTES;

    float acc[2][8][4];
#pragma unroll
    for (int m = 0; m < 2; m++)
#pragma unroll
        for (int n = 0; n < 8; n++)
#pragma unroll
            for (int q = 0; q < 4; q++) acc[m][n][q] = 0.f;

    auto cp_slab = [&](int s) {
        const uint32_t buf = sb + (uint32_t)((s % NBUF) * SLAB_BYTES);
        const uint8_t* as = gA + (size_t)s * IMG_BYTES;
        const uint8_t* ws = gW + (size_t)s * IMG_BYTES;
        const uint32_t off = (uint32_t)t * 16;
        cp16(buf + off,                as + off);
        cp16(buf + 4096 + off,         as + 4096 + off);
        cp16(buf + IMG_BYTES + off,        ws + off);
        cp16(buf + IMG_BYTES + 4096 + off, ws + 4096 + off);
    };

    auto consume = [&](uint32_t buf, int ks) {
        uint32_t afr[2][4], bfr[4][4];
#pragma unroll
        for (int m = 0; m < 2; m++)
            lds128(buf + (uint32_t)(((ks * 8 + wm * 2 + m) * 32 + (lane ^ ks)) * 16),
                   afr[m]);
#pragma unroll
        for (int pp = 0; pp < 4; pp++) {
            const int np = wn * 4 + pp;
            lds128(buf + IMG_BYTES +
                       (uint32_t)(((ks * 8 + np) * 32 + (lane ^ np)) * 16),
                   bfr[pp]);
        }
#pragma unroll
        for (int m = 0; m < 2; m++)
#pragma unroll
            for (int pp = 0; pp < 4; pp++) {
                mma16(acc[m][2 * pp],     afr[m], bfr[pp][0], bfr[pp][1]);
                mma16(acc[m][2 * pp + 1], afr[m], bfr[pp][2], bfr[pp][3]);
            }
    };

    // prologue: 5 slabs in flight
    cp_slab(0); CP_COMMIT();
    cp_slab(1); CP_COMMIT();
    cp_slab(2); CP_COMMIT();
    cp_slab(3); CP_COMMIT();
    cp_slab(4); CP_COMMIT();

    for (int s = 0; s < NSLAB; s++) {
        CP_WAIT4();               // slab s resident (<=4 newer groups pending)
        __syncthreads();          // all warps done with slab s-1's buffer
        if (s + 5 < NSLAB) cp_slab(s + 5);
        CP_COMMIT();              // one group per iteration
        const uint32_t buf = sb + (uint32_t)((s % NBUF) * SLAB_BYTES);
        consume(buf, 0);
        consume(buf, 1);
    }

    // -------- epilogue: bias + LeakyReLU --------
    const int g  = lane >> 2;
    const int tq = lane & 3;
#pragma unroll
    for (int m = 0; m < 2; m++) {
        const int r0 = rB + wm * 32 + m * 16 + g;
#pragma unroll
        for (int nf = 0; nf < 8; nf++) {
            const int col = cB + wn * 64 + nf * 8 + tq * 2;
            const float2 bv = *reinterpret_cast<const float2*>(bias + b * MD + col);
            float v0 = acc[m][nf][0] + bv.x;
            float v1 = acc[m][nf][1] + bv.y;
            float v2 = acc[m][nf][2] + bv.x;
            float v3 = acc[m][nf][3] + bv.y;
            v0 = (v0 >= 0.f) ? v0 : ALPHA * v0;
            v1 = (v1 >= 0.f) ? v1 : ALPHA * v1;
            v2 = (v2 >= 0.f) ? v2 : ALPHA * v2;
            v3 = (v3 >= 0.f) ? v3 : ALPHA * v3;
            *reinterpret_cast<float2*>(out + (size_t)r0 * (NB * MD) + b * MD + col)
                = make_float2(v0, v1);
            *reinterpret_cast<float2*>(out + (size_t)(r0 + 8) * (NB * MD) + b * MD + col)
                = make_float2(v2, v3);
        }
    }
}

} // namespace

extern "C" void kernel_launch(void* const* d_in, const int* in_sizes, int n_in,
                              void* d_out, int out_size)
{
    const float*    x       = (const float*)d_in[0];
    const uint32_t* mask    = (const uint32_t*)d_in[1];
    const float*    embed   = (const float*)d_in[2];
    const float*    batches = (const float*)d_in[3];
    const float*    mean    = (const float*)d_in[4];
    const float*    W       = (const float*)d_in[5];
    const float*    bias    = (const float*)d_in[6];
    float*          out     = (float*)d_out;

    prep_all<<<dim3(NSLAB, 36, NB), 256>>>(x, mask, embed, batches, mean, W);

    cudaFuncSetAttribute(ib_main, cudaFuncAttributeMaxDynamicSharedMemorySize, SMEM_MAIN);
    ib_main<<<dim3(4, 32, NB), 256, SMEM_MAIN>>>(bias, out);
}

// round 9
// speedup vs baseline: 1.7278x; 1.0283x over previous
#include <cuda_runtime.h>
#include <cstdint>

namespace {

constexpr int NB = 4, DIN = 4000, DE = 128, DB = 8;
constexpr int KD = DIN + DE + DB;   // 4136
constexpr int MD = 512;
constexpr float ALPHA = 0.3f;
constexpr int NSLAB = 130;          // 32-K images: 129 real + 1 zero-padded tail
constexpr int NPAIR = 65;           // main consumes image pairs (64 K per stage)
constexpr int IMG_BYTES   = 8192;   // one fp16 fragment image (A or B) per slab per tile
constexpr int STAGE_BYTES = 4 * IMG_BYTES;     // A0 A1 B0 B1 = 32KB
constexpr int NBUF = 3;
constexpr int SMEM_MAIN = NBUF * STAGE_BYTES;  // 96KB

__device__ __align__(16) uint8_t g_Afrag[(size_t)NB * 32 * NSLAB * IMG_BYTES]; // 136MB
__device__ __align__(16) uint8_t g_Wfrag[(size_t)NB * 4  * NSLAB * IMG_BYTES]; // 17MB

__device__ __forceinline__ uint32_t h2pack(float lo, float hi) {  // lo -> low 16 bits
    uint32_t u;
    asm("cvt.rn.f16x2.f32 %0, %1, %2;" : "=r"(u) : "f"(hi), "f"(lo));
    return u;
}
__device__ __forceinline__ uint32_t smem_u32(const void* p) {
    uint32_t a;
    asm("{ .reg .u64 t; cvta.to.shared.u64 t, %1; cvt.u32.u64 %0, t; }" : "=r"(a) : "l"(p));
    return a;
}
__device__ __forceinline__ void sts32(uint32_t a, uint32_t v) {
    asm volatile("st.shared.b32 [%0], %1;" :: "r"(a), "r"(v) : "memory");
}
__device__ __forceinline__ void sts64(uint32_t a, uint32_t v0, uint32_t v1) {
    asm volatile("st.shared.v2.b32 [%0], {%1,%2};" :: "r"(a), "r"(v0), "r"(v1) : "memory");
}
__device__ __forceinline__ void lds128(uint32_t a, uint32_t* r) {
    asm volatile("ld.shared.v4.b32 {%0,%1,%2,%3}, [%4];"
                 : "=r"(r[0]), "=r"(r[1]), "=r"(r[2]), "=r"(r[3]) : "r"(a));
}
__device__ __forceinline__ void mma16(float* d, const uint32_t* a, uint32_t b0, uint32_t b1) {
    asm volatile(
        "mma.sync.aligned.m16n8k16.row.col.f32.f16.f16.f32 "
        "{%0,%1,%2,%3}, {%4,%5,%6,%7}, {%8,%9}, {%0,%1,%2,%3};"
        : "+f"(d[0]), "+f"(d[1]), "+f"(d[2]), "+f"(d[3])
        : "r"(a[0]), "r"(a[1]), "r"(a[2]), "r"(a[3]), "r"(b0), "r"(b1));
}
__device__ __forceinline__ void cp16(uint32_t saddr, const void* gaddr) {
    asm volatile("cp.async.cg.shared.global [%0], [%1], 16;"
                 :: "r"(saddr), "l"(gaddr) : "memory");
}
#define CP_COMMIT() asm volatile("cp.async.commit_group;" ::: "memory")
#define CP_WAIT1()  asm volatile("cp.async.wait_group 1;" ::: "memory")

// ======================= merged prep: A tiles (y<32) + W tiles (y>=32) =======================
// (unchanged from R8 — known-good producer)
__global__ void __launch_bounds__(256)
prep_all(const float* __restrict__ x, const uint32_t* __restrict__ mask,
         const float* __restrict__ embed, const float* __restrict__ batches,
         const float* __restrict__ mean, const float* __restrict__ W)
{
    __shared__ uint32_t sf[2048];    // 8KB image
    const int s  = blockIdx.x;
    const int y  = blockIdx.y;
    const int b  = blockIdx.z;
    const int t  = threadIdx.x;
    const uint32_t base = smem_u32(sf);
    const int k0 = s * 32;

    if (y < 32) {
        // ---------------- A tile ----------------
        const int rB = y * 128;
        if (s < 129) {
            float4 xlo[2], xhi[2], mu[2];
            uint4  mlo[2], mhi[2];
            const bool xreg = (s < 125);
#pragma unroll
            for (int p = 0; p < 2; p++) {
                const int unit = p * 256 + t;
                const int q = unit & 7, pr = unit >> 3;
                const int mf = pr >> 3, rr = pr & 7;
                const int rlo = rB + mf * 16 + rr, rhi = rlo + 8;
                if (xreg) {
                    const int gk = k0 + q * 4;
                    const size_t glo = (size_t)rlo * (NB * DIN) + (size_t)b * DIN + gk;
                    const size_t ghi = (size_t)rhi * (NB * DIN) + (size_t)b * DIN + gk;
                    xlo[p] = *reinterpret_cast<const float4*>(x + glo);
                    xhi[p] = *reinterpret_cast<const float4*>(x + ghi);
                    mlo[p] = *reinterpret_cast<const uint4*>(mask + glo);
                    mhi[p] = *reinterpret_cast<const uint4*>(mask + ghi);
                    mu[p]  = *reinterpret_cast<const float4*>(mean + b * DIN + gk);
                } else {
                    const int e = k0 - DIN + q * 4;
                    xlo[p] = *reinterpret_cast<const float4*>(
                        embed + (size_t)rlo * (NB * DE) + b * DE + e);
                    xhi[p] = *reinterpret_cast<const float4*>(
                        embed + (size_t)rhi * (NB * DE) + b * DE + e);
                }
            }
#pragma unroll
            for (int p = 0; p < 2; p++) {
                const int unit = p * 256 + t;
                const int q = unit & 7, pr = unit >> 3;
                const int mf = pr >> 3, rr = pr & 7;
                float vl[4], vh[4];
                if (xreg) {
                    vl[0] = mlo[p].x ? xlo[p].x - mu[p].x : 0.f;
                    vl[1] = mlo[p].y ? xlo[p].y - mu[p].y : 0.f;
                    vl[2] = mlo[p].z ? xlo[p].z - mu[p].z : 0.f;
                    vl[3] = mlo[p].w ? xlo[p].w - mu[p].w : 0.f;
                    vh[0] = mhi[p].x ? xhi[p].x - mu[p].x : 0.f;
                    vh[1] = mhi[p].y ? xhi[p].y - mu[p].y : 0.f;
                    vh[2] = mhi[p].z ? xhi[p].z - mu[p].z : 0.f;
                    vh[3] = mhi[p].w ? xhi[p].w - mu[p].w : 0.f;
                } else {
                    vl[0] = xlo[p].x; vl[1] = xlo[p].y; vl[2] = xlo[p].z; vl[3] = xlo[p].w;
                    vh[0] = xhi[p].x; vh[1] = xhi[p].y; vh[2] = xhi[p].z; vh[3] = xhi[p].w;
                }
                const uint32_t h0 = h2pack(vl[0], vl[1]);
                const uint32_t h1 = h2pack(vh[0], vh[1]);
                const uint32_t h2 = h2pack(vl[2], vl[3]);
                const uint32_t h3 = h2pack(vh[2], vh[3]);
                const int ks = q >> 2, hi = (q >> 1) & 1, pl = 2 * (q & 1);
                const uint32_t s0 = (uint32_t)((rr * 4 + pl) ^ ks);
                const uint32_t s1 = (uint32_t)((rr * 4 + pl + 1) ^ ks);
                const uint32_t fb = base + (uint32_t)((ks * 8 + mf) * 32) * 16 + hi * 8;
                sts64(fb + s0 * 16, h0, h1);
                sts64(fb + s1 * 16, h2, h3);
            }
        } else {
            float4 blo, bhi;
            int mf = 0, rr = 0, q = 0;
            if (t < 128) {
                const int pr = t >> 1;
                q = t & 1; mf = pr >> 3; rr = pr & 7;
                const int rlo = rB + mf * 16 + rr;
                blo = *reinterpret_cast<const float4*>(batches + (size_t)rlo * DB + q * 4);
                bhi = *reinterpret_cast<const float4*>(batches + (size_t)(rlo + 8) * DB + q * 4);
            }
            for (int i = t; i < 2048; i += 256) sf[i] = 0;
            __syncthreads();
            if (t < 128) {
                const uint32_t h0 = h2pack(blo.x, blo.y);
                const uint32_t h1 = h2pack(bhi.x, bhi.y);
                const uint32_t h2 = h2pack(blo.z, blo.w);
                const uint32_t h3 = h2pack(bhi.z, bhi.w);
                const int pl = 2 * q;
                const uint32_t fb = base + (uint32_t)(mf * 32) * 16;
                sts64(fb + (uint32_t)(rr * 4 + pl) * 16, h0, h1);
                sts64(fb + (uint32_t)(rr * 4 + pl + 1) * 16, h2, h3);
            }
        }
        __syncthreads();
        uint4* dst = reinterpret_cast<uint4*>(
            g_Afrag + ((size_t)(b * 32 + y) * NSLAB + s) * IMG_BYTES);
        const uint4* src = reinterpret_cast<const uint4*>(sf);
        dst[t] = src[t];
        dst[256 + t] = src[256 + t];
    } else {
        // ---------------- W tile ----------------
        const int cbi = y - 32;
        const float* Wb = W + (size_t)b * KD * MD + cbi * 128;
        if (s < 129) {
            float4 w0[2], w1[2];
#pragma unroll
            for (int p = 0; p < 2; p++) {
                const int unit = p * 256 + t;
                const int kp = unit >> 5, n0 = (unit & 31) * 4;
                const int k = k0 + kp * 2;
                w0[p] = *reinterpret_cast<const float4*>(Wb + (size_t)k * MD + n0);
                w1[p] = *reinterpret_cast<const float4*>(Wb + (size_t)(k + 1) * MD + n0);
            }
#pragma unroll
            for (int p = 0; p < 2; p++) {
                const int unit = p * 256 + t;
                const int kp = unit >> 5, n0 = (unit & 31) * 4;
                const int ks = kp >> 3, kpi = kp & 7;
                const int tk = kpi & 3, hi = kpi >> 2;
                const uint32_t h[4] = {h2pack(w0[p].x, w1[p].x), h2pack(w0[p].y, w1[p].y),
                                       h2pack(w0[p].z, w1[p].z), h2pack(w0[p].w, w1[p].w)};
#pragma unroll
                for (int i = 0; i < 4; i++) {
                    const int n = n0 + i, col = n & 7, nf = n >> 3, np = nf >> 1;
                    const int reg = (nf & 1) * 2 + hi;
                    const int slot = (col * 4 + tk) ^ np;
                    sts32(base + (uint32_t)(((ks * 8 + np) * 32 + slot) * 16 + reg * 4),
                          h[i]);
                }
            }
        } else {
            float4 w0, w1;
            int kp = 0, n0 = 0;
            if (t < 128) {
                kp = t >> 5; n0 = (t & 31) * 4;
                const int k = k0 + kp * 2;
                w0 = *reinterpret_cast<const float4*>(Wb + (size_t)k * MD + n0);
                w1 = *reinterpret_cast<const float4*>(Wb + (size_t)(k + 1) * MD + n0);
            }
            for (int i = t; i < 2048; i += 256) sf[i] = 0;
            __syncthreads();
            if (t < 128) {
                const int tk = kp & 3;
                const uint32_t h[4] = {h2pack(w0.x, w1.x), h2pack(w0.y, w1.y),
                                       h2pack(w0.z, w1.z), h2pack(w0.w, w1.w)};
#pragma unroll
                for (int i = 0; i < 4; i++) {
                    const int n = n0 + i, col = n & 7, nf = n >> 3, np = nf >> 1;
                    const int reg = (nf & 1) * 2;
                    const int slot = (col * 4 + tk) ^ np;
                    sts32(base + (uint32_t)((np * 32 + slot) * 16 + reg * 4), h[i]);
                }
            }
        }
        __syncthreads();
        uint4* dst = reinterpret_cast<uint4*>(
            g_Wfrag + ((size_t)(b * 4 + cbi) * NSLAB + s) * IMG_BYTES);
        const uint4* src = reinterpret_cast<const uint4*>(sf);
        dst[t] = src[t];
        dst[256 + t] = src[256 + t];
    }
}

// ======================= main: 64-K pair stages, 3-buffer cp.async ring =======================
__global__ void __launch_bounds__(256, 2)
ib_main(const float* __restrict__ bias, float* __restrict__ out)
{
    extern __shared__ char smem[];
    const uint32_t sb = smem_u32(smem);
    const int t    = threadIdx.x;
    const int lane = t & 31;
    const int wid  = t >> 5;
    const int wm   = wid & 3;        // 32 rows each
    const int wn   = wid >> 2;       // 64 cols each
    const int cbi  = blockIdx.x;
    const int rt   = blockIdx.y;
    const int b    = blockIdx.z;
    const int rB   = rt * 128;
    const int cB   = cbi * 128;

    const uint8_t* gA = g_Afrag + (size_t)(b * 32 + rt) * NSLAB * IMG_BYTES;
    const uint8_t* gW = g_Wfrag + (size_t)(b * 4 + cbi) * NSLAB * IMG_BYTES;

    float acc[2][8][4];
#pragma unroll
    for (int m = 0; m < 2; m++)
#pragma unroll
        for (int n = 0; n < 8; n++)
#pragma unroll
            for (int q = 0; q < 4; q++) acc[m][n][q] = 0.f;

    // stage layout: [A(img0) 8K][A(img1) 8K][B(img0) 8K][B(img1) 8K]
    auto cp_pair = [&](int p) {
        const uint32_t buf = sb + (uint32_t)((p % NBUF) * STAGE_BYTES);
        const uint8_t* as = gA + (size_t)(2 * p) * IMG_BYTES;
        const uint8_t* ws = gW + (size_t)(2 * p) * IMG_BYTES;
        const uint32_t off = (uint32_t)t * 16;
#pragma unroll
        for (int c = 0; c < 4; c++)          // two A images = 4 x 4KB chunks
            cp16(buf + c * 4096 + off, as + c * 4096 + off);
#pragma unroll
        for (int c = 0; c < 4; c++)          // two B images
            cp16(buf + 2 * IMG_BYTES + c * 4096 + off, ws + c * 4096 + off);
    };

    auto consume = [&](uint32_t buf, int img, int ks) {
        const uint32_t abase = buf + (uint32_t)img * IMG_BYTES;
        const uint32_t bbase = buf + 2 * IMG_BYTES + (uint32_t)img * IMG_BYTES;
        uint32_t afr[2][4], bfr[4][4];
#pragma unroll
        for (int m = 0; m < 2; m++)
            lds128(abase + (uint32_t)(((ks * 8 + wm * 2 + m) * 32 + (lane ^ ks)) * 16),
                   afr[m]);
#pragma unroll
        for (int pp = 0; pp < 4; pp++) {
            const int np = wn * 4 + pp;
            lds128(bbase + (uint32_t)(((ks * 8 + np) * 32 + (lane ^ np)) * 16),
                   bfr[pp]);
        }
#pragma unroll
        for (int m = 0; m < 2; m++)
#pragma unroll
            for (int pp = 0; pp < 4; pp++) {
                mma16(acc[m][2 * pp],     afr[m], bfr[pp][0], bfr[pp][1]);
                mma16(acc[m][2 * pp + 1], afr[m], bfr[pp][2], bfr[pp][3]);
            }
    };

    // prologue: 2 pair-stages in flight
    cp_pair(0); CP_COMMIT();
    cp_pair(1); CP_COMMIT();

    for (int p = 0; p < NPAIR; p++) {
        CP_WAIT1();               // stage p resident (<=1 newer group pending)
        __syncthreads();          // all warps done with stage p-1's buffer
        if (p + 2 < NPAIR) cp_pair(p + 2);
        CP_COMMIT();              // one group per iteration
        const uint32_t buf = sb + (uint32_t)((p % NBUF) * STAGE_BYTES);
        consume(buf, 0, 0);
        consume(buf, 0, 1);
        consume(buf, 1, 0);
        consume(buf, 1, 1);
    }

    // -------- epilogue: bias + LeakyReLU --------
    const int g  = lane >> 2;
    const int tq = lane & 3;
#pragma unroll
    for (int m = 0; m < 2; m++) {
        const int r0 = rB + wm * 32 + m * 16 + g;
#pragma unroll
        for (int nf = 0; nf < 8; nf++) {
            const int col = cB + wn * 64 + nf * 8 + tq * 2;
            const float2 bv = *reinterpret_cast<const float2*>(bias + b * MD + col);
            float v0 = acc[m][nf][0] + bv.x;
            float v1 = acc[m][nf][1] + bv.y;
            float v2 = acc[m][nf][2] + bv.x;
            float v3 = acc[m][nf][3] + bv.y;
            v0 = (v0 >= 0.f) ? v0 : ALPHA * v0;
            v1 = (v1 >= 0.f) ? v1 : ALPHA * v1;
            v2 = (v2 >= 0.f) ? v2 : ALPHA * v2;
            v3 = (v3 >= 0.f) ? v3 : ALPHA * v3;
            *reinterpret_cast<float2*>(out + (size_t)r0 * (NB * MD) + b * MD + col)
                = make_float2(v0, v1);
            *reinterpret_cast<float2*>(out + (size_t)(r0 + 8) * (NB * MD) + b * MD + col)
                = make_float2(v2, v3);
        }
    }
}

} // namespace

extern "C" void kernel_launch(void* const* d_in, const int* in_sizes, int n_in,
                              void* d_out, int out_size)
{
    const float*    x       = (const float*)d_in[0];
    const uint32_t* mask    = (const uint32_t*)d_in[1];
    const float*    embed   = (const float*)d_in[2];
    const float*    batches = (const float*)d_in[3];
    const float*    mean    = (const float*)d_in[4];
    const float*    W       = (const float*)d_in[5];
    const float*    bias    = (const float*)d_in[6];
    float*          out     = (float*)d_out;

    prep_all<<<dim3(NSLAB, 36, NB), 256>>>(x, mask, embed, batches, mean, W);

    cudaFuncSetAttribute(ib_main, cudaFuncAttributeMaxDynamicSharedMemorySize, SMEM_MAIN);
    ib_main<<<dim3(4, 32, NB), 256, SMEM_MAIN>>>(bias, out);
}